// round 6
// baseline (speedup 1.0000x reference)
#include <cuda_runtime.h>
#include <cstdint>

// ---------------- problem constants ----------------
#define NN 65536
#define DD 1024
#define KM 64
typedef unsigned long long ull;

// ---------------- device state ----------------
__device__ float  g_x2[NN];
__device__ float  g_dmin[NN];
__device__ int    g_ztmp[NN];
__device__ int    g_z[NN];
__device__ float  g_m2[KM];
__device__ float  g_nc[DD];
__device__ float  g_colpart[64][DD];
__device__ float  g_farpart[512][DD];
__device__ float  g_objpart[8192];
__device__ float  g_sumpart[16][64][KM][64];   // [dchunk16][pblk][k][dsub64]
__device__ int    g_counts[KM];
__device__ int    g_farcnt;
__device__ int    g_K, g_Knew, g_create, g_done, g_it;
__device__ double g_prev;

// ---------------- helpers ----------------
__device__ __forceinline__ ull pk2(float a, float b) {
    ull r; asm("mov.b64 %0, {%1,%2};" : "=l"(r) : "f"(a), "f"(b)); return r;
}
__device__ __forceinline__ void fma2(ull &acc, ull a, ull b) {
    asm("fma.rn.f32x2 %0, %1, %2, %0;" : "+l"(acc) : "l"(a), "l"(b));
}
__device__ __forceinline__ void un2(ull v, float &x, float &y) {
    asm("mov.b64 {%0,%1}, %2;" : "=f"(x), "=f"(y) : "l"(v));
}

// ---------------- init kernels ----------------
__global__ void kI1(const float* __restrict__ X) {
    int tid = threadIdx.x, w = tid >> 5, lane = tid & 31;
    int i = blockIdx.x * 8 + w;
    const float* row = X + (size_t)i * DD;
    float s = 0.f;
#pragma unroll
    for (int j = 0; j < 32; j++) { float v = row[lane + 32 * j]; s = fmaf(v, v, s); }
#pragma unroll
    for (int off = 16; off > 0; off >>= 1) s += __shfl_xor_sync(0xFFFFFFFFu, s, off);
    if (lane == 0) g_x2[i] = s;
}

__global__ void kI2(const float* __restrict__ X) {
    int tid = threadIdx.x;
    float a0 = 0.f, a1 = 0.f, a2 = 0.f, a3 = 0.f;
    int base = blockIdx.x * 1024;
    for (int p = 0; p < 1024; p++) {
        const float* row = X + (size_t)(base + p) * DD;
        a0 += row[tid]; a1 += row[tid + 256]; a2 += row[tid + 512]; a3 += row[tid + 768];
    }
    g_colpart[blockIdx.x][tid]       = a0;
    g_colpart[blockIdx.x][tid + 256] = a1;
    g_colpart[blockIdx.x][tid + 512] = a2;
    g_colpart[blockIdx.x][tid + 768] = a3;
}

__global__ void kI3(float* __restrict__ mu) {
    __shared__ float sm[1024];
    int tid = threadIdx.x;
    float s = 0.f;
    for (int b = 0; b < 64; b++) s += g_colpart[b][tid];
    float m = s * (1.0f / 65536.0f);
    mu[tid] = m;
    for (int k = 1; k < KM; k++) mu[(size_t)k * DD + tid] = 0.f;
    sm[tid] = m * m;
    __syncthreads();
    for (int off = 512; off > 0; off >>= 1) { if (tid < off) sm[tid] += sm[tid + off]; __syncthreads(); }
    if (tid == 0) g_m2[0] = sm[0];
    if (tid >= 1 && tid < KM) g_m2[tid] = 0.f;
    if (tid == 0) { g_K = 1; g_done = 0; g_it = 0; g_prev = 0.0; g_create = 0; g_farcnt = 0; }
}

// ---------------- A: fused GEMM + masked min/argmin ----------------
// 512 blocks x 128 threads; tile 128 points x 64 clusters.
// tx = tid>>4 (k-group), ty = tid&15 (p-group): warp w owns k in [16w,16w+16)
// so warps with 16w >= K skip the entire FMA mainloop.
// Register-staged double buffer: load stage s+1 into regs while computing s.
__global__ __launch_bounds__(128) void kA(const float* __restrict__ X, const float* __restrict__ mu) {
    if (g_done) return;
    if (blockIdx.x == 0 && threadIdx.x == 0) g_farcnt = 0;
    __shared__ float sX[2][16][132];
    __shared__ float sB[2][16][68];
    __shared__ float sx2[128];
    __shared__ float sm2[64];
    __shared__ float srB[128][9];
    __shared__ int   srI[128][9];
    const int tid = threadIdx.x;
    const int tx = tid >> 4, ty = tid & 15, w = tid >> 5;
    const int pbase = blockIdx.x * 128;
    sx2[tid] = g_x2[pbase + tid];
    if (tid < 64) sm2[tid] = g_m2[tid];
    const int K = g_K;
    const int kmaxA = (K + 15) & ~15;
    const bool active = (16 * w) < K;

    ull acc[8][4];
#pragma unroll
    for (int p = 0; p < 8; p++)
#pragma unroll
        for (int q = 0; q < 4; q++) acc[p][q] = 0ull;

    float4 xr[4], br[2];
    // decode indices (const-folded)
    const int xp0 = (tid) >> 2,        xq0 = (tid) & 3;
    const int xp1 = (tid + 128) >> 2,  xq1 = (tid + 128) & 3;
    const int xp2 = (tid + 256) >> 2,  xq2 = (tid + 256) & 3;
    const int xp3 = (tid + 384) >> 2,  xq3 = (tid + 384) & 3;
    const int bk0 = (tid) >> 2,        bq0 = (tid) & 3;
    const int bk1 = (tid + 128) >> 2,  bq1 = (tid + 128) & 3;

    // prologue: load stage 0 into regs, store to buf 0
    xr[0] = *(const float4*)(X + (size_t)(pbase + xp0) * DD + xq0 * 4);
    xr[1] = *(const float4*)(X + (size_t)(pbase + xp1) * DD + xq1 * 4);
    xr[2] = *(const float4*)(X + (size_t)(pbase + xp2) * DD + xq2 * 4);
    xr[3] = *(const float4*)(X + (size_t)(pbase + xp3) * DD + xq3 * 4);
    br[0] = (bk0 < kmaxA) ? *(const float4*)(mu + (size_t)bk0 * DD + bq0 * 4) : make_float4(0.f,0.f,0.f,0.f);
    br[1] = (bk1 < kmaxA) ? *(const float4*)(mu + (size_t)bk1 * DD + bq1 * 4) : make_float4(0.f,0.f,0.f,0.f);
    {
        sX[0][xq0*4+0][xp0]=xr[0].x; sX[0][xq0*4+1][xp0]=xr[0].y; sX[0][xq0*4+2][xp0]=xr[0].z; sX[0][xq0*4+3][xp0]=xr[0].w;
        sX[0][xq1*4+0][xp1]=xr[1].x; sX[0][xq1*4+1][xp1]=xr[1].y; sX[0][xq1*4+2][xp1]=xr[1].z; sX[0][xq1*4+3][xp1]=xr[1].w;
        sX[0][xq2*4+0][xp2]=xr[2].x; sX[0][xq2*4+1][xp2]=xr[2].y; sX[0][xq2*4+2][xp2]=xr[2].z; sX[0][xq2*4+3][xp2]=xr[2].w;
        sX[0][xq3*4+0][xp3]=xr[3].x; sX[0][xq3*4+1][xp3]=xr[3].y; sX[0][xq3*4+2][xp3]=xr[3].z; sX[0][xq3*4+3][xp3]=xr[3].w;
        sB[0][bq0*4+0][bk0]=br[0].x; sB[0][bq0*4+1][bk0]=br[0].y; sB[0][bq0*4+2][bk0]=br[0].z; sB[0][bq0*4+3][bk0]=br[0].w;
        sB[0][bq1*4+0][bk1]=br[1].x; sB[0][bq1*4+1][bk1]=br[1].y; sB[0][bq1*4+2][bk1]=br[1].z; sB[0][bq1*4+3][bk1]=br[1].w;
    }
    __syncthreads();

    for (int s = 0; s < 64; ++s) {
        const int buf = s & 1;
        if (s < 63) {
            const int db = (s + 1) * 16;
            xr[0] = *(const float4*)(X + (size_t)(pbase + xp0) * DD + db + xq0 * 4);
            xr[1] = *(const float4*)(X + (size_t)(pbase + xp1) * DD + db + xq1 * 4);
            xr[2] = *(const float4*)(X + (size_t)(pbase + xp2) * DD + db + xq2 * 4);
            xr[3] = *(const float4*)(X + (size_t)(pbase + xp3) * DD + db + xq3 * 4);
            if (bk0 < kmaxA) br[0] = *(const float4*)(mu + (size_t)bk0 * DD + db + bq0 * 4);
            if (bk1 < kmaxA) br[1] = *(const float4*)(mu + (size_t)bk1 * DD + db + bq1 * 4);
        }
        if (active) {
#pragma unroll
            for (int dd = 0; dd < 16; ++dd) {
                float4 a0 = *reinterpret_cast<const float4*>(&sX[buf][dd][ty * 8]);
                float4 a1 = *reinterpret_cast<const float4*>(&sX[buf][dd][ty * 8 + 4]);
                float4 b0 = *reinterpret_cast<const float4*>(&sB[buf][dd][tx * 8]);
                float4 b1 = *reinterpret_cast<const float4*>(&sB[buf][dd][tx * 8 + 4]);
                ull bp0 = pk2(b0.x, b0.y), bp1 = pk2(b0.z, b0.w);
                ull bp2 = pk2(b1.x, b1.y), bp3 = pk2(b1.z, b1.w);
                float av[8] = {a0.x, a0.y, a0.z, a0.w, a1.x, a1.y, a1.z, a1.w};
#pragma unroll
                for (int p = 0; p < 8; p++) {
                    ull xx = pk2(av[p], av[p]);
                    fma2(acc[p][0], xx, bp0);
                    fma2(acc[p][1], xx, bp1);
                    fma2(acc[p][2], xx, bp2);
                    fma2(acc[p][3], xx, bp3);
                }
            }
        }
        __syncthreads();
        if (s < 63) {
            const int nb = buf ^ 1;
            sX[nb][xq0*4+0][xp0]=xr[0].x; sX[nb][xq0*4+1][xp0]=xr[0].y; sX[nb][xq0*4+2][xp0]=xr[0].z; sX[nb][xq0*4+3][xp0]=xr[0].w;
            sX[nb][xq1*4+0][xp1]=xr[1].x; sX[nb][xq1*4+1][xp1]=xr[1].y; sX[nb][xq1*4+2][xp1]=xr[1].z; sX[nb][xq1*4+3][xp1]=xr[1].w;
            sX[nb][xq2*4+0][xp2]=xr[2].x; sX[nb][xq2*4+1][xp2]=xr[2].y; sX[nb][xq2*4+2][xp2]=xr[2].z; sX[nb][xq2*4+3][xp2]=xr[2].w;
            sX[nb][xq3*4+0][xp3]=xr[3].x; sX[nb][xq3*4+1][xp3]=xr[3].y; sX[nb][xq3*4+2][xp3]=xr[3].z; sX[nb][xq3*4+3][xp3]=xr[3].w;
            sB[nb][bq0*4+0][bk0]=br[0].x; sB[nb][bq0*4+1][bk0]=br[0].y; sB[nb][bq0*4+2][bk0]=br[0].z; sB[nb][bq0*4+3][bk0]=br[0].w;
            sB[nb][bq1*4+0][bk1]=br[1].x; sB[nb][bq1*4+1][bk1]=br[1].y; sB[nb][bq1*4+2][bk1]=br[1].z; sB[nb][bq1*4+3][bk1]=br[1].w;
            __syncthreads();
        }
    }

    // epilogue: dist = (x2 - 2S) + m2, mask k>=K, per-thread min, cross-warp smem argmin
#pragma unroll
    for (int p = 0; p < 8; p++) {
        int prow = ty * 8 + p;
        float x2v = sx2[prow];
        float best = 3.0e38f; int bidx = 0;
#pragma unroll
        for (int q = 0; q < 4; q++) {
            float s0, s1; un2(acc[p][q], s0, s1);
            int k0 = tx * 8 + q * 2;
            float d0 = fmaf(-2.f, s0, x2v) + sm2[k0];
            float d1 = fmaf(-2.f, s1, x2v) + sm2[k0 + 1];
            if (k0 < K && d0 < best) { best = d0; bidx = k0; }
            if (k0 + 1 < K && d1 < best) { best = d1; bidx = k0 + 1; }
        }
        srB[prow][tx] = best; srI[prow][tx] = bidx;
    }
    __syncthreads();
    {
        float bb = srB[tid][0]; int bi = srI[tid][0];
#pragma unroll
        for (int t = 1; t < 8; t++) {
            float v = srB[tid][t];
            if (v < bb) { bb = v; bi = srI[tid][t]; }   // ascending k-range scan: first-index ties
        }
        g_dmin[pbase + tid] = bb;
        g_ztmp[pbase + tid] = bi;
    }
}

// ---------------- B1: masked sum of far points (partials), 512 blocks ----------------
__global__ void kB1(const float* __restrict__ X) {
    if (g_done) return;
    int tid = threadIdx.x;                 // 256
    float a0 = 0.f, a1 = 0.f, a2 = 0.f, a3 = 0.f;
    int base = blockIdx.x * 128;
    int cnt = 0;
    for (int p = 0; p < 128; p++) {
        int i = base + p;
        if (g_dmin[i] > 1000.0f) {
            const float* row = X + (size_t)i * DD;
            a0 += row[tid]; a1 += row[tid + 256]; a2 += row[tid + 512]; a3 += row[tid + 768];
            cnt++;
        }
    }
    g_farpart[blockIdx.x][tid]       = a0;
    g_farpart[blockIdx.x][tid + 256] = a1;
    g_farpart[blockIdx.x][tid + 512] = a2;
    g_farpart[blockIdx.x][tid + 768] = a3;
    if (tid == 0) atomicAdd(&g_farcnt, cnt);
}

// ---------------- B2: new center, create flag, reset counts ----------------
__global__ void kB2() {
    if (g_done) return;
    int tid = threadIdx.x;       // 1024
    float s = 0.f;
#pragma unroll 8
    for (int b = 0; b < 512; b++) s += g_farpart[b][tid];
    int cnt = g_farcnt;
    g_nc[tid] = s / fmaxf((float)cnt, 1.0f);
    if (tid < KM) g_counts[tid] = 0;
    if (tid == 0) {
        int K = g_K;
        int create = (cnt > 0 && K < KM) ? 1 : 0;
        g_create = create;
        g_Knew = K + create;
    }
}

// ---------------- C1: finalize z/dvals, counts, obj partials ----------------
__global__ void kC1(const float* __restrict__ X) {
    if (g_done) return;
    __shared__ int sh[KM];
    __shared__ float wv[8];
    int tid = threadIdx.x, w = tid >> 5, lane = tid & 31;
    if (tid < KM) sh[tid] = 0;
    __syncthreads();
    int i = blockIdx.x * 8 + w;
    int create = g_create;
    int K = g_K;
    float dm = g_dmin[i];
    float dval; int z;
    bool cf = (create != 0) && (dm > 1000.0f);
    if (cf) {
        const float* row = X + (size_t)i * DD;
        float s = 0.f;
#pragma unroll
        for (int j = 0; j < 32; j++) {
            int d = lane + 32 * j;
            float dv = row[d] - g_nc[d];
            s = fmaf(dv, dv, s);
        }
#pragma unroll
        for (int off = 16; off > 0; off >>= 1) s += __shfl_xor_sync(0xFFFFFFFFu, s, off);
        dval = s; z = K;
    } else { dval = dm; z = g_ztmp[i]; }
    if (lane == 0) { g_z[i] = z; atomicAdd(&sh[z], 1); wv[w] = dval; }
    __syncthreads();
    if (tid == 0) {
        float s = 0.f;
        for (int q = 0; q < 8; q++) s += wv[q];
        g_objpart[blockIdx.x] = s;
    }
    if (tid < KM && sh[tid]) atomicAdd(&g_counts[tid], sh[tid]);
}

// ---------------- C2: deterministic scatter-sum partials ----------------
// grid (16 dchunks, 64 pblocks) x 128 threads. Two half-blocks (even/odd points)
// accumulate into separate smem copies -> breaks the same-address RMW chain.
__global__ __launch_bounds__(128) void kC2(const float* __restrict__ X) {
    if (g_done) return;
    __shared__ float acc[2][KM][64];    // 32KB
    __shared__ int zs[128];
    int tid = threadIdx.x;
    int h = tid >> 6, dl = tid & 63;
    int kmax = min(KM, (g_Knew + 15) & ~15);
    int dbase = blockIdx.x * 64;
    int pb = blockIdx.y * 1024;
    for (int k = 0; k < kmax; k++) acc[h][k][dl] = 0.f;
    for (int t0 = 0; t0 < 8; t0++) {
        __syncthreads();
        zs[tid] = g_z[pb + t0 * 128 + tid];
        __syncthreads();
#pragma unroll 4
        for (int jj = 0; jj < 64; jj++) {
            int j = jj * 2 + h;
            float v = X[(size_t)(pb + t0 * 128 + j) * DD + dbase + dl];
            acc[h][zs[j]][dl] += v;
        }
    }
    __syncthreads();
    for (int k = h; k < kmax; k += 2)
        g_sumpart[blockIdx.x][blockIdx.y][k][dl] = acc[0][k][dl] + acc[1][k][dl];
}

// ---------------- D: centroid update + m2 (blocks 0..63) and obj/convergence (block 64) ----------------
__global__ void kD(float* __restrict__ mu) {
    if (g_done) return;
    __shared__ float sm[256];
    __shared__ double sd[256];
    int tid = threadIdx.x, bx = blockIdx.x;
    if (bx < KM) {
        int kmax = min(KM, (g_Knew + 15) & ~15);
        if (bx >= kmax) return;
        int cnt = g_counts[bx];
#pragma unroll
        for (int j = 0; j < 4; j++) {
            int d = tid + 256 * j;
            float s = 0.f;
#pragma unroll 8
            for (int pbk = 0; pbk < 64; pbk++) s += g_sumpart[d >> 6][pbk][bx][d & 63];
            if (cnt > 0) mu[(size_t)bx * DD + d] = s / (float)cnt;
        }
        float ss = 0.f;
#pragma unroll
        for (int j = 0; j < 4; j++) {
            float m = mu[(size_t)bx * DD + tid + 256 * j];
            ss = fmaf(m, m, ss);
        }
        sm[tid] = ss;
        __syncthreads();
        for (int off = 128; off > 0; off >>= 1) { if (tid < off) sm[tid] += sm[tid + off]; __syncthreads(); }
        if (tid == 0) g_m2[bx] = sm[0];
    } else {
        double s = 0.0;
#pragma unroll 8
        for (int j = 0; j < 32; j++) s += (double)g_objpart[tid * 32 + j];
        sd[tid] = s;
        __syncthreads();
        for (int off = 128; off > 0; off >>= 1) { if (tid < off) sd[tid] += sd[tid + off]; __syncthreads(); }
        if (tid == 0) {
            int Kn = g_Knew;
            double obj = sd[0] + 1000.0 * (double)Kn;
            int it = g_it;
            bool conv = (it > 0) && (fabs(obj - g_prev) < 1e-3 * obj);
            g_prev = obj;
            g_K = Kn;
            g_it = it + 1;
            if (conv) g_done = 1;
        }
    }
}

// ---------------- launch ----------------
extern "C" void kernel_launch(void* const* d_in, const int* in_sizes, int n_in,
                              void* d_out, int out_size) {
    const float* X = (const float*)d_in[0];
    float* mu = (float*)d_out;   // d_out (1,64,1024) doubles as the live centroid buffer

    kI1<<<NN / 8, 256>>>(X);
    kI2<<<64, 256>>>(X);
    kI3<<<1, 1024>>>(mu);

    for (int t = 0; t < 50; t++) {
        kA<<<NN / 128, 128>>>(X, mu);
        kB1<<<512, 256>>>(X);
        kB2<<<1, 1024>>>();
        kC1<<<NN / 8, 256>>>(X);
        kC2<<<dim3(16, 64), 128>>>(X);
        kD<<<KM + 1, 256>>>(mu);
    }
}

// round 8
// speedup vs baseline: 1.1524x; 1.1524x over previous
#include <cuda_runtime.h>
#include <cstdint>

// ---------------- problem constants ----------------
#define NN 65536
#define DD 1024
#define KM 64
typedef unsigned long long ull;

// ---------------- device state ----------------
__device__ float  g_x2[NN];
__device__ float  g_dmin[NN];
__device__ int    g_ztmp[NN];
__device__ int    g_z[NN];
__device__ float  g_m2[KM];
__device__ float  g_nc[DD];
__device__ float  g_colpart[64][DD];
__device__ float  g_farpart[128][DD];
__device__ float  g_objpart[8192];
__device__ float  g_sumpart[8][64][KM][128];   // [dchunk][pblk][k][dsub]
__device__ int    g_counts[KM];
__device__ int    g_farcnt;
__device__ int    g_K, g_Knew, g_create, g_done, g_it;
__device__ double g_prev;

// ---------------- helpers ----------------
__device__ __forceinline__ ull pk2(float a, float b) {
    ull r; asm("mov.b64 %0, {%1,%2};" : "=l"(r) : "f"(a), "f"(b)); return r;
}
__device__ __forceinline__ void fma2(ull &acc, ull a, ull b) {
    asm("fma.rn.f32x2 %0, %1, %2, %0;" : "+l"(acc) : "l"(a), "l"(b));
}
__device__ __forceinline__ void un2(ull v, float &x, float &y) {
    asm("mov.b64 {%0,%1}, %2;" : "=f"(x), "=f"(y) : "l"(v));
}
__device__ __forceinline__ void cpa16(uint32_t dst, const float* src) {
    asm volatile("cp.async.cg.shared.global [%0], [%1], 16;\n" :: "r"(dst), "l"(src));
}
__device__ __forceinline__ void cpa_commit() {
    asm volatile("cp.async.commit_group;\n" ::: "memory");
}
template<int N> __device__ __forceinline__ void cpa_wait() {
    asm volatile("cp.async.wait_group %0;\n" :: "n"(N) : "memory");
}

// ---------------- init kernels ----------------
__global__ void kI1(const float* __restrict__ X) {
    int tid = threadIdx.x, w = tid >> 5, lane = tid & 31;
    int i = blockIdx.x * 8 + w;
    const float* row = X + (size_t)i * DD;
    float s = 0.f;
#pragma unroll
    for (int j = 0; j < 32; j++) { float v = row[lane + 32 * j]; s = fmaf(v, v, s); }
#pragma unroll
    for (int off = 16; off > 0; off >>= 1) s += __shfl_xor_sync(0xFFFFFFFFu, s, off);
    if (lane == 0) g_x2[i] = s;
}

__global__ void kI2(const float* __restrict__ X) {
    int tid = threadIdx.x;
    float a0 = 0.f, a1 = 0.f, a2 = 0.f, a3 = 0.f;
    int base = blockIdx.x * 1024;
    for (int p = 0; p < 1024; p++) {
        const float* row = X + (size_t)(base + p) * DD;
        a0 += row[tid]; a1 += row[tid + 256]; a2 += row[tid + 512]; a3 += row[tid + 768];
    }
    g_colpart[blockIdx.x][tid]       = a0;
    g_colpart[blockIdx.x][tid + 256] = a1;
    g_colpart[blockIdx.x][tid + 512] = a2;
    g_colpart[blockIdx.x][tid + 768] = a3;
}

__global__ void kI3(float* __restrict__ mu) {
    __shared__ float sm[1024];
    int tid = threadIdx.x;
    float s = 0.f;
    for (int b = 0; b < 64; b++) s += g_colpart[b][tid];
    float m = s * (1.0f / 65536.0f);
    mu[tid] = m;
    for (int k = 1; k < KM; k++) mu[(size_t)k * DD + tid] = 0.f;
    sm[tid] = m * m;
    __syncthreads();
    for (int off = 512; off > 0; off >>= 1) { if (tid < off) sm[tid] += sm[tid + off]; __syncthreads(); }
    if (tid == 0) g_m2[0] = sm[0];
    if (tid >= 1 && tid < KM) g_m2[tid] = 0.f;
    if (tid == 0) { g_K = 1; g_done = 0; g_it = 0; g_prev = 0.0; g_create = 0; g_farcnt = 0; }
}

// ---------------- A: fused GEMM + masked min/argmin (cp.async 4-stage ring) ----------------
// 512 blocks x 128 threads; tile 128 points x 64 clusters; 8 dims per stage, 128 stages.
// Warp w owns clusters [16w,16w+16) -> warps with 16w >= K skip all FMA work.
// Lanes own points (lane, lane+32, lane+64, lane+96). X stays row-major in smem
// (12-float padded rows: LDS.128 stride 3 (16B units), coprime with 8 -> conflict-free).
// B reads are warp-uniform broadcasts. Per-(i,k) accumulation is a serial fp32 chain
// in strictly ascending d -> bit-identical to previous passing kernels.
#define NSTG 4
__global__ __launch_bounds__(128) void kA(const float* __restrict__ X, const float* __restrict__ mu) {
    if (g_done) return;
    if (blockIdx.x == 0 && threadIdx.x == 0) g_farcnt = 0;
    __shared__ float sX[NSTG][128][12];   // 24 KB
    __shared__ float sB[NSTG][64][12];    // 12 KB
    __shared__ float sm2[64];
    __shared__ float srB[128][5];
    __shared__ int   srI[128][5];
    const int tid = threadIdx.x;
    const int w = tid >> 5, lane = tid & 31;
    const int pbase = blockIdx.x * 128;
    if (tid < 64) sm2[tid] = g_m2[tid];
    const int K = g_K;
    const int kmaxA = (K + 15) & ~15;
    const int kbase = 16 * w;
    const bool active = kbase < K;

    // smem byte bases for cp.async
    const uint32_t sx0 = (uint32_t)__cvta_generic_to_shared(&sX[0][0][0]);
    const uint32_t sb0 = (uint32_t)__cvta_generic_to_shared(&sB[0][0][0]);
    // X copy: chunk c in {tid, tid+128}: p=c>>1, q=c&1  (16 rows x 32B per warp, coalesced)
    const int xp0 = tid >> 1,        xq0 = tid & 1;
    const int xp1 = (tid + 128) >> 1, xq1 = (tid + 128) & 1;
    // B copy: chunk tid: k=tid>>1, q=tid&1, predicated on k<kmaxA
    const int bk = tid >> 1, bq = tid & 1;
    const bool bpred = bk < kmaxA;
    const float* Xr0 = X + (size_t)(pbase + xp0) * DD + 4 * xq0;
    const float* Xr1 = X + (size_t)(pbase + xp1) * DD + 4 * xq1;
    const float* Br  = mu + (size_t)bk * DD + 4 * bq;
    const uint32_t dx0 = sx0 + (uint32_t)(xp0 * 48 + 16 * xq0);
    const uint32_t dx1 = sx0 + (uint32_t)(xp1 * 48 + 16 * xq1);
    const uint32_t dbb = sb0 + (uint32_t)(bk * 48 + 16 * bq);

    ull acc[4][8];
#pragma unroll
    for (int p = 0; p < 4; p++)
#pragma unroll
        for (int m = 0; m < 8; m++) acc[p][m] = 0ull;

    // prologue: issue stages 0..2
#pragma unroll
    for (int s = 0; s < 3; s++) {
        const int db = s * 8;
        const uint32_t so = (uint32_t)(s * 6144);
        const uint32_t sob = (uint32_t)(s * 3072);
        cpa16(dx0 + so, Xr0 + db);
        cpa16(dx1 + so, Xr1 + db);
        if (bpred) cpa16(dbb + sob, Br + db);
        cpa_commit();
    }

    for (int s = 0; s < 128; ++s) {
        cpa_wait<2>();            // stage s resident (per-thread)
        __syncthreads();          // collective visibility; also fences slot reuse
        if (s < 125) {            // issue stage s+3 into slot (s+3)&3 (== slot of stage s-1)
            const int sn = s + 3;
            const int db = sn * 8;
            const uint32_t so = (uint32_t)((sn & 3) * 6144);
            const uint32_t sob = (uint32_t)((sn & 3) * 3072);
            cpa16(dx0 + so, Xr0 + db);
            cpa16(dx1 + so, Xr1 + db);
            if (bpred) cpa16(dbb + sob, Br + db);
        }
        cpa_commit();             // commit (possibly empty) to keep group accounting uniform
        if (active) {
            const int slot = s & 3;
#pragma unroll
            for (int q4 = 0; q4 < 2; ++q4) {
                float4 xv[4];
#pragma unroll
                for (int j = 0; j < 4; j++)
                    xv[j] = *reinterpret_cast<const float4*>(&sX[slot][lane + 32 * j][q4 * 4]);
                ull xp[4][4];
#pragma unroll
                for (int j = 0; j < 4; j++) {
                    xp[j][0] = pk2(xv[j].x, xv[j].x);
                    xp[j][1] = pk2(xv[j].y, xv[j].y);
                    xp[j][2] = pk2(xv[j].z, xv[j].z);
                    xp[j][3] = pk2(xv[j].w, xv[j].w);
                }
#pragma unroll
                for (int m = 0; m < 8; m++) {
                    float4 bA = *reinterpret_cast<const float4*>(&sB[slot][kbase + 2 * m][q4 * 4]);
                    float4 bB = *reinterpret_cast<const float4*>(&sB[slot][kbase + 2 * m + 1][q4 * 4]);
                    ull bp0 = pk2(bA.x, bB.x), bp1 = pk2(bA.y, bB.y);
                    ull bp2 = pk2(bA.z, bB.z), bp3 = pk2(bA.w, bB.w);
#pragma unroll
                    for (int p = 0; p < 4; p++) {
                        fma2(acc[p][m], xp[p][0], bp0);
                        fma2(acc[p][m], xp[p][1], bp1);
                        fma2(acc[p][m], xp[p][2], bp2);
                        fma2(acc[p][m], xp[p][3], bp3);
                    }
                }
            }
        }
    }

    // epilogue: dist = (x2 - 2S) + m2, mask k>=K, per-thread min over own k-group,
    // then cross-warp (ascending-k => first-index ties) reduce in smem.
    if (active) {
#pragma unroll
        for (int j = 0; j < 4; j++) {
            int prow = lane + 32 * j;
            float x2v = g_x2[pbase + prow];
            float best = 3.0e38f; int bidx = 0;
#pragma unroll
            for (int m = 0; m < 8; m++) {
                float s0, s1; un2(acc[j][m], s0, s1);
                int k0 = kbase + 2 * m;
                float d0 = fmaf(-2.f, s0, x2v) + sm2[k0];
                float d1 = fmaf(-2.f, s1, x2v) + sm2[k0 + 1];
                if (k0 < K && d0 < best) { best = d0; bidx = k0; }
                if (k0 + 1 < K && d1 < best) { best = d1; bidx = k0 + 1; }
            }
            srB[prow][w] = best; srI[prow][w] = bidx;
        }
    }
    __syncthreads();
    {
        const int nw = (K + 15) >> 4;
        float bb = srB[tid][0]; int bi = srI[tid][0];
        for (int t = 1; t < nw; t++) {
            float v = srB[tid][t];
            if (v < bb) { bb = v; bi = srI[tid][t]; }
        }
        g_dmin[pbase + tid] = bb;
        g_ztmp[pbase + tid] = bi;
    }
}

// ---------------- B1: masked sum of far points (partials) ----------------
__global__ void kB1(const float* __restrict__ X) {
    if (g_done) return;
    int tid = threadIdx.x;
    float a0 = 0.f, a1 = 0.f, a2 = 0.f, a3 = 0.f;
    int base = blockIdx.x * 512;
    int cnt = 0;
    for (int p = 0; p < 512; p++) {
        int i = base + p;
        if (g_dmin[i] > 1000.0f) {
            const float* row = X + (size_t)i * DD;
            a0 += row[tid]; a1 += row[tid + 256]; a2 += row[tid + 512]; a3 += row[tid + 768];
            cnt++;
        }
    }
    g_farpart[blockIdx.x][tid]       = a0;
    g_farpart[blockIdx.x][tid + 256] = a1;
    g_farpart[blockIdx.x][tid + 512] = a2;
    g_farpart[blockIdx.x][tid + 768] = a3;
    if (tid == 0) atomicAdd(&g_farcnt, cnt);
}

// ---------------- B2: new center, create flag, reset counts ----------------
__global__ void kB2() {
    if (g_done) return;
    int tid = threadIdx.x;       // 1024
    float s = 0.f;
    for (int b = 0; b < 128; b++) s += g_farpart[b][tid];
    int cnt = g_farcnt;
    g_nc[tid] = s / fmaxf((float)cnt, 1.0f);
    if (tid < KM) g_counts[tid] = 0;
    if (tid == 0) {
        int K = g_K;
        int create = (cnt > 0 && K < KM) ? 1 : 0;
        g_create = create;
        g_Knew = K + create;
    }
}

// ---------------- C1: finalize z/dvals, counts, obj partials ----------------
__global__ void kC1(const float* __restrict__ X) {
    if (g_done) return;
    __shared__ int sh[KM];
    __shared__ float wv[8];
    int tid = threadIdx.x, w = tid >> 5, lane = tid & 31;
    if (tid < KM) sh[tid] = 0;
    __syncthreads();
    int i = blockIdx.x * 8 + w;
    int create = g_create;
    int K = g_K;
    float dm = g_dmin[i];
    float dval; int z;
    bool cf = (create != 0) && (dm > 1000.0f);
    if (cf) {
        const float* row = X + (size_t)i * DD;
        float s = 0.f;
#pragma unroll
        for (int j = 0; j < 32; j++) {
            int d = lane + 32 * j;
            float dv = row[d] - g_nc[d];
            s = fmaf(dv, dv, s);
        }
#pragma unroll
        for (int off = 16; off > 0; off >>= 1) s += __shfl_xor_sync(0xFFFFFFFFu, s, off);
        dval = s; z = K;            // Kc == K (create implies K < KM)
    } else { dval = dm; z = g_ztmp[i]; }
    if (lane == 0) { g_z[i] = z; atomicAdd(&sh[z], 1); wv[w] = dval; }
    __syncthreads();
    if (tid == 0) {
        float s = 0.f;
        for (int q = 0; q < 8; q++) s += wv[q];
        g_objpart[blockIdx.x] = s;
    }
    if (tid < KM && sh[tid]) atomicAdd(&g_counts[tid], sh[tid]);
}

// ---------------- C2: deterministic scatter-sum partials ----------------
__global__ __launch_bounds__(128) void kC2(const float* __restrict__ X) {
    if (g_done) return;
    __shared__ float acc[KM * 128];
    __shared__ int zs[128];
    int tid = threadIdx.x;
    int dbase = blockIdx.x * 128;
    int pb = blockIdx.y * 1024;
#pragma unroll
    for (int k = 0; k < KM; k++) acc[k * 128 + tid] = 0.f;
    for (int t0 = 0; t0 < 1024; t0 += 128) {
        __syncthreads();
        zs[tid] = g_z[pb + t0 + tid];
        __syncthreads();
#pragma unroll 4
        for (int j = 0; j < 128; j++) {
            float v = X[(size_t)(pb + t0 + j) * DD + dbase + tid];
            acc[zs[j] * 128 + tid] += v;
        }
    }
    __syncthreads();
    for (int k = 0; k < KM; k++)
        g_sumpart[blockIdx.x][blockIdx.y][k][tid] = acc[k * 128 + tid];
}

// ---------------- D1: centroid update + m2 ----------------
__global__ void kD1(float* __restrict__ mu) {
    if (g_done) return;
    __shared__ float sm[256];
    int k = blockIdx.x, tid = threadIdx.x;   // 256 threads
    int cnt = g_counts[k];
#pragma unroll
    for (int j = 0; j < 4; j++) {
        int d = tid + 256 * j;
        float s = 0.f;
        for (int pb = 0; pb < 64; pb++) s += g_sumpart[d >> 7][pb][k][d & 127];
        if (cnt > 0) mu[(size_t)k * DD + d] = s / (float)cnt;
    }
    float ss = 0.f;
#pragma unroll
    for (int j = 0; j < 4; j++) {
        float m = mu[(size_t)k * DD + tid + 256 * j];
        ss = fmaf(m, m, ss);
    }
    sm[tid] = ss;
    __syncthreads();
    for (int off = 128; off > 0; off >>= 1) { if (tid < off) sm[tid] += sm[tid + off]; __syncthreads(); }
    if (tid == 0) g_m2[k] = sm[0];
}

// ---------------- D2: objective, convergence, commit scalars ----------------
__global__ void kD2() {
    if (g_done) return;
    __shared__ double sd[1024];
    int tid = threadIdx.x;
    double s = 0.0;
#pragma unroll
    for (int j = 0; j < 8; j++) s += (double)g_objpart[tid * 8 + j];
    sd[tid] = s;
    __syncthreads();
    for (int off = 512; off > 0; off >>= 1) { if (tid < off) sd[tid] += sd[tid + off]; __syncthreads(); }
    if (tid == 0) {
        int Kn = g_Knew;
        double obj = sd[0] + 1000.0 * (double)Kn;
        int it = g_it;
        bool conv = (it > 0) && (fabs(obj - g_prev) < 1e-3 * obj);
        g_prev = obj;
        g_K = Kn;
        g_it = it + 1;
        if (conv) g_done = 1;
    }
}

// ---------------- launch ----------------
extern "C" void kernel_launch(void* const* d_in, const int* in_sizes, int n_in,
                              void* d_out, int out_size) {
    const float* X = (const float*)d_in[0];
    float* mu = (float*)d_out;   // d_out (1,64,1024) doubles as the live centroid buffer

    kI1<<<NN / 8, 256>>>(X);
    kI2<<<64, 256>>>(X);
    kI3<<<1, 1024>>>(mu);

    for (int t = 0; t < 50; t++) {
        kA<<<NN / 128, 128>>>(X, mu);
        kB1<<<128, 256>>>(X);
        kB2<<<1, 1024>>>();
        kC1<<<NN / 8, 256>>>(X);
        kC2<<<dim3(8, 64), 128>>>(X);
        kD1<<<KM, 256>>>(mu);
        kD2<<<1, 1024>>>();
    }
}

// round 11
// speedup vs baseline: 1.1952x; 1.0372x over previous
#include <cuda_runtime.h>
#include <cstdint>

// ---------------- problem constants ----------------
#define NN 65536
#define DD 1024
#define KM 64
typedef unsigned long long ull;

// ---------------- device state ----------------
__device__ float  g_x2[NN];
__device__ float  g_dmin[NN];
__device__ int    g_ztmp[NN];
__device__ int    g_z[NN];
__device__ float  g_m2[KM];
__device__ float  g_nc[DD];
__device__ float  g_colpart[64][DD];
__device__ float  g_farpart[128][DD];
__device__ float  g_objpart[8192];
__device__ float  g_sumpart[8][64][KM][128];   // [dchunk][pblk][k][dsub]
__device__ int    g_counts[KM];
__device__ int    g_farcnt;
__device__ int    g_K, g_Knew, g_create, g_done, g_it;
__device__ double g_prev;

// ---------------- helpers ----------------
__device__ __forceinline__ ull pk2(float a, float b) {
    ull r; asm("mov.b64 %0, {%1,%2};" : "=l"(r) : "f"(a), "f"(b)); return r;
}
__device__ __forceinline__ void fma2(ull &acc, ull a, ull b) {
    asm("fma.rn.f32x2 %0, %1, %2, %0;" : "+l"(acc) : "l"(a), "l"(b));
}
__device__ __forceinline__ void un2(ull v, float &x, float &y) {
    asm("mov.b64 {%0,%1}, %2;" : "=f"(x), "=f"(y) : "l"(v));
}
__device__ __forceinline__ void cpa16(uint32_t dst, const float* src) {
    asm volatile("cp.async.cg.shared.global [%0], [%1], 16;\n" :: "r"(dst), "l"(src));
}
__device__ __forceinline__ void cpa_commit() {
    asm volatile("cp.async.commit_group;\n" ::: "memory");
}
template<int N> __device__ __forceinline__ void cpa_wait() {
    asm volatile("cp.async.wait_group %0;\n" :: "n"(N) : "memory");
}

// ---------------- init kernels ----------------
__global__ void kI1(const float* __restrict__ X) {
    int tid = threadIdx.x, w = tid >> 5, lane = tid & 31;
    int i = blockIdx.x * 8 + w;
    const float* row = X + (size_t)i * DD;
    float s = 0.f;
#pragma unroll
    for (int j = 0; j < 32; j++) { float v = row[lane + 32 * j]; s = fmaf(v, v, s); }
#pragma unroll
    for (int off = 16; off > 0; off >>= 1) s += __shfl_xor_sync(0xFFFFFFFFu, s, off);
    if (lane == 0) g_x2[i] = s;
}

__global__ void kI2(const float* __restrict__ X) {
    int tid = threadIdx.x;
    float a0 = 0.f, a1 = 0.f, a2 = 0.f, a3 = 0.f;
    int base = blockIdx.x * 1024;
    for (int p = 0; p < 1024; p++) {
        const float* row = X + (size_t)(base + p) * DD;
        a0 += row[tid]; a1 += row[tid + 256]; a2 += row[tid + 512]; a3 += row[tid + 768];
    }
    g_colpart[blockIdx.x][tid]       = a0;
    g_colpart[blockIdx.x][tid + 256] = a1;
    g_colpart[blockIdx.x][tid + 512] = a2;
    g_colpart[blockIdx.x][tid + 768] = a3;
}

__global__ void kI3(float* __restrict__ mu) {
    __shared__ float sm[1024];
    int tid = threadIdx.x;
    float s = 0.f;
    for (int b = 0; b < 64; b++) s += g_colpart[b][tid];
    float m = s * (1.0f / 65536.0f);
    mu[tid] = m;
    for (int k = 1; k < KM; k++) mu[(size_t)k * DD + tid] = 0.f;
    sm[tid] = m * m;
    __syncthreads();
    for (int off = 512; off > 0; off >>= 1) { if (tid < off) sm[tid] += sm[tid + off]; __syncthreads(); }
    if (tid == 0) g_m2[0] = sm[0];
    if (tid >= 1 && tid < KM) g_m2[tid] = 0.f;
    if (tid == 0) { g_K = 1; g_done = 0; g_it = 0; g_prev = 0.0; g_create = 0; g_farcnt = 0; }
}

// ---------------- A: fused GEMM + masked min/argmin ----------------
// 128 blocks x 256 threads; 512 points/block; 16-dim stages, 64 stages, 3-slot cp.async ring.
// Warp w owns points [64w, 64w+64) (2 per lane) and computes ALL clusters of the
// current 16-wide k-group -> all 4 SMSPs run FMA. Outer kg loop (re-streaming X)
// covers K>16; in practice K<=16 so it runs once. X rows padded to 20 floats
// (bank starts 20L mod 32 distinct per 8-lane phase -> conflict-free LDS.128).
// Per-(i,k) accumulation is a serial fp32 chain in strictly ascending d ->
// bit-identical distances to all prior passing kernels.
#define XPITCH 20
#define STGX (512 * XPITCH * 4)      // 40960 B per X stage
#define STGB (16 * 16 * 4)           // 1024 B per B stage
__global__ __launch_bounds__(256) void kA(const float* __restrict__ X, const float* __restrict__ mu) {
    if (g_done) return;
    if (blockIdx.x == 0 && threadIdx.x == 0) g_farcnt = 0;
    __shared__ float sX[3 * 512 * XPITCH];   // 120 KB
    __shared__ float sB[3 * 16 * 16];        // 3 KB
    __shared__ float sm2[64];
    const int tid = threadIdx.x;
    const int w = tid >> 5, lane = tid & 31;
    const int pbase = blockIdx.x * 512;
    if (tid < 64) sm2[tid] = g_m2[tid];
    const int K = g_K;
    const int nkg = (K + 15) >> 4;

    const uint32_t sx0 = (uint32_t)__cvta_generic_to_shared(&sX[0]);
    const uint32_t sb0 = (uint32_t)__cvta_generic_to_shared(&sB[0]);

    // X copy plan: 2048 16B-chunks/stage, 8 per thread; chunk c: row=c>>2, q=c&3
    const float* Xr[8];
    uint32_t dx[8];
#pragma unroll
    for (int j = 0; j < 8; j++) {
        int c = tid + 256 * j;
        int row = c >> 2, q = c & 3;
        Xr[j] = X + (size_t)(pbase + row) * DD + 4 * q;
        dx[j] = sx0 + (uint32_t)(row * (XPITCH * 4) + 16 * q);
    }
    // B copy plan: 64 chunks/stage, threads 0..63; k_local=tid>>2, q=tid&3
    const int bkl = tid >> 2, bq = tid & 3;
    const bool bthr = tid < 64;
    const uint32_t dbb = sb0 + (uint32_t)(bkl * 64 + 16 * bq);

    // per-point running best (kept across k-groups; ascending k => first-index ties)
    const int p0 = 64 * w + lane;           // local point row 0
    float best0 = 3.0e38f, best1 = 3.0e38f;
    int bidx0 = 0, bidx1 = 0;

    for (int kg = 0; kg < nkg; kg++) {
        const int kbase = 16 * kg;
        const float* Br = mu + (size_t)(kbase + bkl) * DD + 4 * bq;

        ull acc0[8], acc1[8];
#pragma unroll
        for (int m = 0; m < 8; m++) { acc0[m] = 0ull; acc1[m] = 0ull; }

        __syncthreads();   // all compute on previous pass/iteration done before refilling slots
        // prologue: stages 0,1
#pragma unroll
        for (int s = 0; s < 2; s++) {
            const int db = s * 16;
            const uint32_t ox = (uint32_t)(s * STGX), ob = (uint32_t)(s * STGB);
#pragma unroll
            for (int j = 0; j < 8; j++) cpa16(dx[j] + ox, Xr[j] + db);
            if (bthr) cpa16(dbb + ob, Br + db);
            cpa_commit();
        }

        for (int s = 0; s < 64; ++s) {
            cpa_wait<1>();
            __syncthreads();
            if (s < 62) {
                const int sn = s + 2;
                const int db = sn * 16;
                const int slot = sn - (sn >= 3 ? 3 : 0) - (sn >= 6 ? 0 : 0); // placeholder
                const int sl = sn % 3;
                const uint32_t ox = (uint32_t)(sl * STGX), ob = (uint32_t)(sl * STGB);
#pragma unroll
                for (int j = 0; j < 8; j++) cpa16(dx[j] + ox, Xr[j] + db);
                if (bthr) cpa16(dbb + ob, Br + db);
            }
            cpa_commit();
            {
                const int sl = s % 3;
                const float* xb0 = &sX[sl * 512 * XPITCH + p0 * XPITCH];
                const float* xb1 = xb0 + 32 * XPITCH;
                const float* bb = &sB[sl * 256];
#pragma unroll
                for (int q = 0; q < 4; q++) {
                    float4 x0 = *reinterpret_cast<const float4*>(xb0 + 4 * q);
                    float4 x1 = *reinterpret_cast<const float4*>(xb1 + 4 * q);
                    ull xp0[4], xp1[4];
                    xp0[0] = pk2(x0.x, x0.x); xp0[1] = pk2(x0.y, x0.y);
                    xp0[2] = pk2(x0.z, x0.z); xp0[3] = pk2(x0.w, x0.w);
                    xp1[0] = pk2(x1.x, x1.x); xp1[1] = pk2(x1.y, x1.y);
                    xp1[2] = pk2(x1.z, x1.z); xp1[3] = pk2(x1.w, x1.w);
#pragma unroll
                    for (int m = 0; m < 8; m++) {
                        float4 bA = *reinterpret_cast<const float4*>(bb + (2 * m) * 16 + 4 * q);
                        float4 bBv = *reinterpret_cast<const float4*>(bb + (2 * m + 1) * 16 + 4 * q);
                        ull bp0 = pk2(bA.x, bBv.x), bp1 = pk2(bA.y, bBv.y);
                        ull bp2 = pk2(bA.z, bBv.z), bp3 = pk2(bA.w, bBv.w);
                        fma2(acc0[m], xp0[0], bp0); fma2(acc0[m], xp0[1], bp1);
                        fma2(acc0[m], xp0[2], bp2); fma2(acc0[m], xp0[3], bp3);
                        fma2(acc1[m], xp1[0], bp0); fma2(acc1[m], xp1[1], bp1);
                        fma2(acc1[m], xp1[2], bp2); fma2(acc1[m], xp1[3], bp3);
                    }
                }
            }
        }

        // epilogue for this k-group: dist = (x2 - 2S) + m2, mask k>=K, update best
        {
            float x2v0 = g_x2[pbase + p0];
            float x2v1 = g_x2[pbase + p0 + 32];
#pragma unroll
            for (int m = 0; m < 8; m++) {
                int k0 = kbase + 2 * m;
                float s0, s1; un2(acc0[m], s0, s1);
                float d0 = fmaf(-2.f, s0, x2v0) + sm2[k0];
                float d1 = fmaf(-2.f, s1, x2v0) + sm2[k0 + 1];
                if (k0 < K && d0 < best0) { best0 = d0; bidx0 = k0; }
                if (k0 + 1 < K && d1 < best0) { best0 = d1; bidx0 = k0 + 1; }
                un2(acc1[m], s0, s1);
                float e0 = fmaf(-2.f, s0, x2v1) + sm2[k0];
                float e1 = fmaf(-2.f, s1, x2v1) + sm2[k0 + 1];
                if (k0 < K && e0 < best1) { best1 = e0; bidx1 = k0; }
                if (k0 + 1 < K && e1 < best1) { best1 = e1; bidx1 = k0 + 1; }
            }
        }
    }

    g_dmin[pbase + p0] = best0;      g_ztmp[pbase + p0] = bidx0;
    g_dmin[pbase + p0 + 32] = best1; g_ztmp[pbase + p0 + 32] = bidx1;
}

// ---------------- B1: masked sum of far points (partials) ----------------
__global__ void kB1(const float* __restrict__ X) {
    if (g_done) return;
    int tid = threadIdx.x;
    float a0 = 0.f, a1 = 0.f, a2 = 0.f, a3 = 0.f;
    int base = blockIdx.x * 512;
    int cnt = 0;
    for (int p = 0; p < 512; p++) {
        int i = base + p;
        if (g_dmin[i] > 1000.0f) {
            const float* row = X + (size_t)i * DD;
            a0 += row[tid]; a1 += row[tid + 256]; a2 += row[tid + 512]; a3 += row[tid + 768];
            cnt++;
        }
    }
    g_farpart[blockIdx.x][tid]       = a0;
    g_farpart[blockIdx.x][tid + 256] = a1;
    g_farpart[blockIdx.x][tid + 512] = a2;
    g_farpart[blockIdx.x][tid + 768] = a3;
    if (tid == 0) atomicAdd(&g_farcnt, cnt);
}

// ---------------- B2: new center, create flag, reset counts ----------------
__global__ void kB2() {
    if (g_done) return;
    int tid = threadIdx.x;       // 1024
    float s = 0.f;
    for (int b = 0; b < 128; b++) s += g_farpart[b][tid];
    int cnt = g_farcnt;
    g_nc[tid] = s / fmaxf((float)cnt, 1.0f);
    if (tid < KM) g_counts[tid] = 0;
    if (tid == 0) {
        int K = g_K;
        int create = (cnt > 0 && K < KM) ? 1 : 0;
        g_create = create;
        g_Knew = K + create;
    }
}

// ---------------- C1: finalize z/dvals, counts, obj partials ----------------
__global__ void kC1(const float* __restrict__ X) {
    if (g_done) return;
    __shared__ int sh[KM];
    __shared__ float wv[8];
    int tid = threadIdx.x, w = tid >> 5, lane = tid & 31;
    if (tid < KM) sh[tid] = 0;
    __syncthreads();
    int i = blockIdx.x * 8 + w;
    int create = g_create;
    int K = g_K;
    float dm = g_dmin[i];
    float dval; int z;
    bool cf = (create != 0) && (dm > 1000.0f);
    if (cf) {
        const float* row = X + (size_t)i * DD;
        float s = 0.f;
#pragma unroll
        for (int j = 0; j < 32; j++) {
            int d = lane + 32 * j;
            float dv = row[d] - g_nc[d];
            s = fmaf(dv, dv, s);
        }
#pragma unroll
        for (int off = 16; off > 0; off >>= 1) s += __shfl_xor_sync(0xFFFFFFFFu, s, off);
        dval = s; z = K;            // Kc == K (create implies K < KM)
    } else { dval = dm; z = g_ztmp[i]; }
    if (lane == 0) { g_z[i] = z; atomicAdd(&sh[z], 1); wv[w] = dval; }
    __syncthreads();
    if (tid == 0) {
        float s = 0.f;
        for (int q = 0; q < 8; q++) s += wv[q];
        g_objpart[blockIdx.x] = s;
    }
    if (tid < KM && sh[tid]) atomicAdd(&g_counts[tid], sh[tid]);
}

// ---------------- C2: deterministic scatter-sum partials ----------------
__global__ __launch_bounds__(128) void kC2(const float* __restrict__ X) {
    if (g_done) return;
    __shared__ float acc[KM * 128];
    __shared__ int zs[128];
    int tid = threadIdx.x;
    int dbase = blockIdx.x * 128;
    int pb = blockIdx.y * 1024;
#pragma unroll
    for (int k = 0; k < KM; k++) acc[k * 128 + tid] = 0.f;
    for (int t0 = 0; t0 < 1024; t0 += 128) {
        __syncthreads();
        zs[tid] = g_z[pb + t0 + tid];
        __syncthreads();
#pragma unroll 4
        for (int j = 0; j < 128; j++) {
            float v = X[(size_t)(pb + t0 + j) * DD + dbase + tid];
            acc[zs[j] * 128 + tid] += v;
        }
    }
    __syncthreads();
    for (int k = 0; k < KM; k++)
        g_sumpart[blockIdx.x][blockIdx.y][k][tid] = acc[k * 128 + tid];
}

// ---------------- D1: centroid update + m2 ----------------
__global__ void kD1(float* __restrict__ mu) {
    if (g_done) return;
    __shared__ float sm[256];
    int k = blockIdx.x, tid = threadIdx.x;   // 256 threads
    int cnt = g_counts[k];
#pragma unroll
    for (int j = 0; j < 4; j++) {
        int d = tid + 256 * j;
        float s = 0.f;
        for (int pb = 0; pb < 64; pb++) s += g_sumpart[d >> 7][pb][k][d & 127];
        if (cnt > 0) mu[(size_t)k * DD + d] = s / (float)cnt;
    }
    float ss = 0.f;
#pragma unroll
    for (int j = 0; j < 4; j++) {
        float m = mu[(size_t)k * DD + tid + 256 * j];
        ss = fmaf(m, m, ss);
    }
    sm[tid] = ss;
    __syncthreads();
    for (int off = 128; off > 0; off >>= 1) { if (tid < off) sm[tid] += sm[tid + off]; __syncthreads(); }
    if (tid == 0) g_m2[k] = sm[0];
}

// ---------------- D2: objective, convergence, commit scalars ----------------
__global__ void kD2() {
    if (g_done) return;
    __shared__ double sd[1024];
    int tid = threadIdx.x;
    double s = 0.0;
#pragma unroll
    for (int j = 0; j < 8; j++) s += (double)g_objpart[tid * 8 + j];
    sd[tid] = s;
    __syncthreads();
    for (int off = 512; off > 0; off >>= 1) { if (tid < off) sd[tid] += sd[tid + off]; __syncthreads(); }
    if (tid == 0) {
        int Kn = g_Knew;
        double obj = sd[0] + 1000.0 * (double)Kn;
        int it = g_it;
        bool conv = (it > 0) && (fabs(obj - g_prev) < 1e-3 * obj);
        g_prev = obj;
        g_K = Kn;
        g_it = it + 1;
        if (conv) g_done = 1;
    }
}

// ---------------- launch ----------------
extern "C" void kernel_launch(void* const* d_in, const int* in_sizes, int n_in,
                              void* d_out, int out_size) {
    const float* X = (const float*)d_in[0];
    float* mu = (float*)d_out;   // d_out (1,64,1024) doubles as the live centroid buffer

    kI1<<<NN / 8, 256>>>(X);
    kI2<<<64, 256>>>(X);
    kI3<<<1, 1024>>>(mu);

    for (int t = 0; t < 50; t++) {
        kA<<<NN / 512, 256>>>(X, mu);
        kB1<<<128, 256>>>(X);
        kB2<<<1, 1024>>>();
        kC1<<<NN / 8, 256>>>(X);
        kC2<<<dim3(8, 64), 128>>>(X);
        kD1<<<KM, 256>>>(mu);
        kD2<<<1, 1024>>>();
    }
}

// round 12
// speedup vs baseline: 1.9864x; 1.6619x over previous
#include <cuda_runtime.h>
#include <cstdint>

// ---------------- problem constants ----------------
#define NN 65536
#define DD 1024
#define KM 64
#define NBLK 128
typedef unsigned long long ull;

// ---------------- device state ----------------
__device__ float  g_x2[NN];
__device__ float  g_dmin[NN];
__device__ int    g_ztmp[NN];
__device__ float  g_m2[KM];
__device__ float  g_colpart[64][DD];
__device__ float  g_objA[64];
__device__ float  g_objF[NBLK];
__device__ float  g_sumpart[8][64][KM][128];   // [dchunk][pblk][k][dsub]
__device__ int    g_counts[KM];
__device__ int    g_anyfar;
__device__ int    g_K, g_done;
__device__ double g_prev;
__device__ unsigned g_barcnt;
__device__ volatile unsigned g_bargen;

// ---------------- helpers ----------------
__device__ __forceinline__ ull pk2(float a, float b) {
    ull r; asm("mov.b64 %0, {%1,%2};" : "=l"(r) : "f"(a), "f"(b)); return r;
}
__device__ __forceinline__ void fma2(ull &acc, ull a, ull b) {
    asm("fma.rn.f32x2 %0, %1, %2, %0;" : "+l"(acc) : "l"(a), "l"(b));
}
__device__ __forceinline__ void un2(ull v, float &x, float &y) {
    asm("mov.b64 {%0,%1}, %2;" : "=f"(x), "=f"(y) : "l"(v));
}
__device__ __forceinline__ void cpa16(uint32_t dst, const float* src) {
    asm volatile("cp.async.cg.shared.global [%0], [%1], 16;\n" :: "r"(dst), "l"(src));
}
__device__ __forceinline__ void cpa_commit() {
    asm volatile("cp.async.commit_group;\n" ::: "memory");
}
template<int N> __device__ __forceinline__ void cpa_wait() {
    asm volatile("cp.async.wait_group %0;\n" :: "n"(N) : "memory");
}
__device__ __forceinline__ float vldf(const float* p) { return *(volatile const float*)p; }
__device__ __forceinline__ int   vldi(const int* p)   { return *(volatile const int*)p; }

// grid-wide barrier: all NBLK blocks resident (1 block/SM, 128 <= 148 SMs)
__device__ __forceinline__ void gbar(unsigned &gen) {
    __syncthreads();
    if (threadIdx.x == 0) {
        gen++;
        __threadfence();
        unsigned t = atomicAdd(&g_barcnt, 1);
        if (t == NBLK - 1) {
            g_barcnt = 0;
            __threadfence();
            g_bargen = gen;
        } else {
            while (g_bargen < gen) { __nanosleep(20); }
            __threadfence();
        }
    }
    __syncthreads();
}

// ---------------- init kernels ----------------
__global__ void kI1(const float* __restrict__ X) {
    int tid = threadIdx.x, w = tid >> 5, lane = tid & 31;
    int i = blockIdx.x * 8 + w;
    const float* row = X + (size_t)i * DD;
    float s = 0.f;
#pragma unroll
    for (int j = 0; j < 32; j++) { float v = row[lane + 32 * j]; s = fmaf(v, v, s); }
#pragma unroll
    for (int off = 16; off > 0; off >>= 1) s += __shfl_xor_sync(0xFFFFFFFFu, s, off);
    if (lane == 0) g_x2[i] = s;
}

__global__ void kI2(const float* __restrict__ X) {
    int tid = threadIdx.x;
    float a0 = 0.f, a1 = 0.f, a2 = 0.f, a3 = 0.f;
    int base = blockIdx.x * 1024;
    for (int p = 0; p < 1024; p++) {
        const float* row = X + (size_t)(base + p) * DD;
        a0 += row[tid]; a1 += row[tid + 256]; a2 += row[tid + 512]; a3 += row[tid + 768];
    }
    g_colpart[blockIdx.x][tid]       = a0;
    g_colpart[blockIdx.x][tid + 256] = a1;
    g_colpart[blockIdx.x][tid + 512] = a2;
    g_colpart[blockIdx.x][tid + 768] = a3;
}

__global__ void kI3(float* __restrict__ mu) {
    __shared__ float sm[1024];
    int tid = threadIdx.x;
    float s = 0.f;
    for (int b = 0; b < 64; b++) s += g_colpart[b][tid];
    float m = s * (1.0f / 65536.0f);
    mu[tid] = m;
    for (int k = 1; k < KM; k++) mu[(size_t)k * DD + tid] = 0.f;
    sm[tid] = m * m;
    __syncthreads();
    for (int off = 512; off > 0; off >>= 1) { if (tid < off) sm[tid] += sm[tid + off]; __syncthreads(); }
    if (tid == 0) g_m2[0] = sm[0];
    if (tid >= 1 && tid < KM) g_m2[tid] = 0.f;
    if (tid < KM) g_counts[tid] = 0;
    if (tid == 0) {
        g_K = 1; g_done = 0; g_prev = 0.0; g_anyfar = 0;
        g_barcnt = 0; g_bargen = 0;
    }
}

// ---------------- persistent mega-kernel ----------------
// Phases per active iteration (5 grid barriers):
//  A : fused GEMM + masked min/argmin (identical math to R11 kA) + anyfar flag
//  C2': vectorized scatter-sum partials + counts + non-cf obj partials
//  D1': centroid update + m2 (cluster Kc's centroid == new_center)
//  F : cf-point dvals vs new center (create iterations only)
//  G : obj reduce (double), convergence, commit K/done, reset flags
#define XPITCH 20
#define STGX (512 * XPITCH * 4)
#define STGB (16 * 16 * 4)
__global__ __launch_bounds__(256) void kMega(const float* __restrict__ X, float* __restrict__ mu) {
    __shared__ __align__(16) float sraw[31616];   // ~123.5 KB, aliased per phase
    const int tid = threadIdx.x, bid = blockIdx.x;
    const int w = tid >> 5, lane = tid & 31;
    unsigned gen = 0;

    // --- phase-A persistent layout ---
    float* sX  = sraw;             // 30720 floats
    float* sB  = sraw + 30720;     // 768
    float* sm2 = sraw + 31488;     // 64
    const int pbase = bid * 512;
    const uint32_t sx0 = (uint32_t)__cvta_generic_to_shared(sX);
    const uint32_t sb0 = (uint32_t)__cvta_generic_to_shared(sB);
    const float* Xr[8]; uint32_t dxo[8];
#pragma unroll
    for (int j = 0; j < 8; j++) {
        int c = tid + 256 * j;
        int row = c >> 2, q = c & 3;
        Xr[j] = X + (size_t)(pbase + row) * DD + 4 * q;
        dxo[j] = sx0 + (uint32_t)(row * (XPITCH * 4) + 16 * q);
    }
    const int bkl = tid >> 2, bq = tid & 3;
    const bool bthr = tid < 64;
    const uint32_t dbb = sb0 + (uint32_t)(bkl * 64 + 16 * bq);
    const int p0 = 64 * w + lane;

    for (int iter = 0; iter < 50; ++iter) {
        if (vldi(&g_done)) break;
        const int K = vldi(&g_K);

        // ===================== Phase A =====================
        if (tid < 64) sm2[tid] = vldf(g_m2 + tid);
        const int nkg = (K + 15) >> 4;
        float best0 = 3.0e38f, best1 = 3.0e38f;
        int bidx0 = 0, bidx1 = 0;

        for (int kg = 0; kg < nkg; kg++) {
            const int kbase = 16 * kg;
            const float* Br = mu + (size_t)(kbase + bkl) * DD + 4 * bq;
            ull acc0[8], acc1[8];
#pragma unroll
            for (int m = 0; m < 8; m++) { acc0[m] = 0ull; acc1[m] = 0ull; }

            __syncthreads();
#pragma unroll
            for (int s = 0; s < 2; s++) {
                const int db = s * 16;
                const uint32_t ox = (uint32_t)(s * STGX), ob = (uint32_t)(s * STGB);
#pragma unroll
                for (int j = 0; j < 8; j++) cpa16(dxo[j] + ox, Xr[j] + db);
                if (bthr) cpa16(dbb + ob, Br + db);
                cpa_commit();
            }

            for (int s = 0; s < 64; ++s) {
                cpa_wait<1>();
                __syncthreads();
                if (s < 62) {
                    const int sn = s + 2;
                    const int db = sn * 16;
                    const int sl = sn % 3;
                    const uint32_t ox = (uint32_t)(sl * STGX), ob = (uint32_t)(sl * STGB);
#pragma unroll
                    for (int j = 0; j < 8; j++) cpa16(dxo[j] + ox, Xr[j] + db);
                    if (bthr) cpa16(dbb + ob, Br + db);
                }
                cpa_commit();
                {
                    const int sl = s % 3;
                    const float* xb0 = &sX[sl * 512 * XPITCH + p0 * XPITCH];
                    const float* xb1 = xb0 + 32 * XPITCH;
                    const float* bb = &sB[sl * 256];
#pragma unroll
                    for (int q = 0; q < 4; q++) {
                        float4 x0 = *reinterpret_cast<const float4*>(xb0 + 4 * q);
                        float4 x1 = *reinterpret_cast<const float4*>(xb1 + 4 * q);
                        ull xp0[4], xp1[4];
                        xp0[0] = pk2(x0.x, x0.x); xp0[1] = pk2(x0.y, x0.y);
                        xp0[2] = pk2(x0.z, x0.z); xp0[3] = pk2(x0.w, x0.w);
                        xp1[0] = pk2(x1.x, x1.x); xp1[1] = pk2(x1.y, x1.y);
                        xp1[2] = pk2(x1.z, x1.z); xp1[3] = pk2(x1.w, x1.w);
#pragma unroll
                        for (int m = 0; m < 8; m++) {
                            float4 bA  = *reinterpret_cast<const float4*>(bb + (2 * m) * 16 + 4 * q);
                            float4 bBv = *reinterpret_cast<const float4*>(bb + (2 * m + 1) * 16 + 4 * q);
                            ull bp0 = pk2(bA.x, bBv.x), bp1 = pk2(bA.y, bBv.y);
                            ull bp2 = pk2(bA.z, bBv.z), bp3 = pk2(bA.w, bBv.w);
                            fma2(acc0[m], xp0[0], bp0); fma2(acc0[m], xp0[1], bp1);
                            fma2(acc0[m], xp0[2], bp2); fma2(acc0[m], xp0[3], bp3);
                            fma2(acc1[m], xp1[0], bp0); fma2(acc1[m], xp1[1], bp1);
                            fma2(acc1[m], xp1[2], bp2); fma2(acc1[m], xp1[3], bp3);
                        }
                    }
                }
            }

            {
                float x2v0 = g_x2[pbase + p0];
                float x2v1 = g_x2[pbase + p0 + 32];
#pragma unroll
                for (int m = 0; m < 8; m++) {
                    int k0 = kbase + 2 * m;
                    float s0, s1; un2(acc0[m], s0, s1);
                    float d0 = fmaf(-2.f, s0, x2v0) + sm2[k0];
                    float d1 = fmaf(-2.f, s1, x2v0) + sm2[k0 + 1];
                    if (k0 < K && d0 < best0) { best0 = d0; bidx0 = k0; }
                    if (k0 + 1 < K && d1 < best0) { best0 = d1; bidx0 = k0 + 1; }
                    un2(acc1[m], s0, s1);
                    float e0 = fmaf(-2.f, s0, x2v1) + sm2[k0];
                    float e1 = fmaf(-2.f, s1, x2v1) + sm2[k0 + 1];
                    if (k0 < K && e0 < best1) { best1 = e0; bidx1 = k0; }
                    if (k0 + 1 < K && e1 < best1) { best1 = e1; bidx1 = k0 + 1; }
                }
            }
        }

        g_dmin[pbase + p0] = best0;       g_ztmp[pbase + p0] = bidx0;
        g_dmin[pbase + p0 + 32] = best1;  g_ztmp[pbase + p0 + 32] = bidx1;
        {
            bool farflag = (best0 > 1000.f) || (best1 > 1000.f);
            unsigned b = __ballot_sync(0xFFFFFFFFu, farflag);
            if (b && lane == 0) atomicOr(&g_anyfar, 1);
        }
        gbar(gen);

        // ------- iteration bookkeeping (computed redundantly, no race) -------
        const int create = (vldi(&g_anyfar) != 0) && (K < KM);
        const int Kc = K;
        const int Knew = K + create;
        const int kmax = min(KM, (Knew + 15) & ~15);
        const int nk2 = kmax >> 4;

        // ===================== Phase C2' =====================
        {
            const int h = tid >> 7, t128 = tid & 127;
            float4* acc4 = reinterpret_cast<float4*>(sraw) + h * 2048;  // [pg4][16][32] f4 per half
            int* zsh  = reinterpret_cast<int*>(sraw + 16384) + h * 1024;
            int* scnt = reinterpret_cast<int*>(sraw + 18432);           // 64 ints
            float* ored = sraw + 18496;                                  // 256 floats
            if (bid < 64 && tid < 64) scnt[tid] = 0;
            float objs = 0.f;
            const int c = t128 & 31, pg = t128 >> 5;

            for (int jo = 0; jo < 2; jo++) {
                const int unit = (jo * 2 + h) * 128 + bid;
                const int dchunk = unit >> 6, pblk = unit & 63;
                const int dbase = dchunk * 128, pb = pblk * 1024;
                const bool docount = (jo == 0) && (h == 0) && (bid < 64);
                __syncthreads();
#pragma unroll
                for (int q = 0; q < 8; q++) {
                    int ip = pb + q * 128 + t128;
                    float dmv = vldf(g_dmin + ip);
                    int ztv = vldi(g_ztmp + ip);
                    bool cf = create && (dmv > 1000.f);
                    int z = cf ? Kc : ztv;
                    zsh[q * 128 + t128] = z;
                    if (docount) { atomicAdd(&scnt[z], 1); if (!cf) objs += dmv; }
                }
                const float* xp = X + (size_t)(pb + pg * 256) * DD + dbase + 4 * c;
                for (int kg2 = 0; kg2 < nk2; kg2++) {
                    __syncthreads();
#pragma unroll
                    for (int kk = 0; kk < 16; kk++)
                        acc4[(pg * 16 + kk) * 32 + c] = make_float4(0.f, 0.f, 0.f, 0.f);
                    __syncthreads();
#pragma unroll 4
                    for (int t = 0; t < 256; t++) {
                        float4 v = *reinterpret_cast<const float4*>(xp + (size_t)t * DD);
                        int zr = zsh[pg * 256 + t] - (kg2 << 4);
                        if ((unsigned)zr < 16u) {
                            float4 a = acc4[(pg * 16 + zr) * 32 + c];
                            a.x += v.x; a.y += v.y; a.z += v.z; a.w += v.w;
                            acc4[(pg * 16 + zr) * 32 + c] = a;
                        }
                    }
                    __syncthreads();
#pragma unroll
                    for (int kb = 0; kb < 16; kb += 4) {
                        int kloc = kb + (t128 >> 5);
                        float4 s0 = acc4[(0 * 16 + kloc) * 32 + c];
                        float4 s1 = acc4[(1 * 16 + kloc) * 32 + c];
                        float4 s2 = acc4[(2 * 16 + kloc) * 32 + c];
                        float4 s3 = acc4[(3 * 16 + kloc) * 32 + c];
                        float4 o;
                        o.x = ((s0.x + s1.x) + s2.x) + s3.x;
                        o.y = ((s0.y + s1.y) + s2.y) + s3.y;
                        o.z = ((s0.z + s1.z) + s2.z) + s3.z;
                        o.w = ((s0.w + s1.w) + s2.w) + s3.w;
                        *reinterpret_cast<float4*>(&g_sumpart[dchunk][pblk][kg2 * 16 + kloc][4 * c]) = o;
                    }
                }
            }
            __syncthreads();
            if (bid < 64) {
                ored[tid] = (h == 0) ? objs : 0.f;
                __syncthreads();
                for (int off = 128; off > 0; off >>= 1) { if (tid < off) ored[tid] += ored[tid + off]; __syncthreads(); }
                if (tid == 0) g_objA[bid] = ored[0];
                if (tid < 64 && scnt[tid]) atomicAdd(&g_counts[tid], scnt[tid]);
            }
        }
        gbar(gen);

        // ===================== Phase D1' =====================
        if (bid < kmax) {
            float* smr = sraw;
            const int k = bid;
            const int cnt = vldi(g_counts + k);
            float ss = 0.f;
#pragma unroll
            for (int jo2 = 0; jo2 < 4; jo2++) {
                int d = tid + 256 * jo2;
                float s = 0.f;
#pragma unroll 8
                for (int pb2 = 0; pb2 < 64; pb2++)
                    s += vldf(&g_sumpart[d >> 7][pb2][k][d & 127]);
                float mv;
                if (cnt > 0) { mv = s / (float)cnt; mu[(size_t)k * DD + d] = mv; }
                else mv = vldf(&mu[(size_t)k * DD + d]);
                ss = fmaf(mv, mv, ss);
            }
            smr[tid] = ss;
            __syncthreads();
            for (int off = 128; off > 0; off >>= 1) { if (tid < off) smr[tid] += smr[tid + off]; __syncthreads(); }
            if (tid == 0) g_m2[k] = smr[0];
        }
        gbar(gen);

        // ===================== Phase F =====================
        if (create) {
            float* snc = sraw;           // 1024
            float* wred = sraw + 1024;   // 8
#pragma unroll
            for (int jo2 = 0; jo2 < 4; jo2++)
                snc[tid + 256 * jo2] = vldf(&mu[(size_t)Kc * DD + tid + 256 * jo2]);
            __syncthreads();
            float objw = 0.f;
            for (int t = 0; t < 64; t++) {
                int i = pbase + w * 64 + t;
                float dmv = vldf(g_dmin + i);
                if (dmv > 1000.f) {
                    const float* row = X + (size_t)i * DD;
                    float s = 0.f;
#pragma unroll
                    for (int j = 0; j < 32; j++) {
                        int d = lane + 32 * j;
                        float dv = row[d] - snc[d];
                        s = fmaf(dv, dv, s);
                    }
#pragma unroll
                    for (int off = 16; off > 0; off >>= 1) s += __shfl_xor_sync(0xFFFFFFFFu, s, off);
                    objw += s;
                }
            }
            if (lane == 0) wred[w] = objw;
            __syncthreads();
            if (tid == 0) {
                float s = 0.f;
                for (int q = 0; q < 8; q++) s += wred[q];
                g_objF[bid] = s;
            }
        } else if (tid == 0) g_objF[bid] = 0.f;
        gbar(gen);

        // ===================== Phase G =====================
        if (bid == 0) {
            double* sd = reinterpret_cast<double*>(sraw);
            double v = 0.0;
            if (tid < 64) v += (double)vldf(g_objA + tid);
            if (tid >= 64 && tid < 64 + NBLK) v += (double)vldf(g_objF + (tid - 64));
            sd[tid] = v;
            __syncthreads();
            for (int off = 128; off > 0; off >>= 1) { if (tid < off) sd[tid] += sd[tid + off]; __syncthreads(); }
            if (tid == 0) {
                double obj = sd[0] + 1000.0 * (double)Knew;
                bool conv = (iter > 0) && (fabs(obj - g_prev) < 1e-3 * obj);
                g_prev = obj;
                *(volatile int*)&g_K = Knew;
                *(volatile int*)&g_anyfar = 0;
                if (conv) *(volatile int*)&g_done = 1;
            }
            if (tid < 64) *(volatile int*)(g_counts + tid) = 0;
        }
        gbar(gen);
    }
}

// ---------------- launch ----------------
extern "C" void kernel_launch(void* const* d_in, const int* in_sizes, int n_in,
                              void* d_out, int out_size) {
    const float* X = (const float*)d_in[0];
    float* mu = (float*)d_out;   // d_out (1,64,1024) doubles as the live centroid buffer

    kI1<<<NN / 8, 256>>>(X);
    kI2<<<64, 256>>>(X);
    kI3<<<1, 1024>>>(mu);
    kMega<<<NBLK, 256>>>(X, mu);
}

// round 15
// speedup vs baseline: 2.5161x; 1.2667x over previous
#include <cuda_runtime.h>
#include <cstdint>

// ---------------- problem constants ----------------
#define NN 65536
#define DD 1024
#define KM 64
#define NBLK 128
typedef unsigned long long ull;

// ---------------- device state ----------------
__device__ float  g_x2[NN];
__device__ float  g_dmin[NN];
__device__ int    g_ztmp[NN];
__device__ float  g_m2[KM];
__device__ float  g_colpart2[NBLK][DD];
__device__ float  g_objA[64];
__device__ float  g_objF[NBLK];
__device__ float  g_sumpart[8][64][KM][128];   // [dchunk][pblk][k][dsub]
__device__ int    g_counts[KM];
__device__ int    g_anyfar;
__device__ int    g_K, g_done;
__device__ double g_prev;
__device__ unsigned g_barcnt;
__device__ volatile unsigned g_bargen;

// ---------------- helpers ----------------
__device__ __forceinline__ ull pk2(float a, float b) {
    ull r; asm("mov.b64 %0, {%1,%2};" : "=l"(r) : "f"(a), "f"(b)); return r;
}
__device__ __forceinline__ void fma2(ull &acc, ull a, ull b) {
    asm("fma.rn.f32x2 %0, %1, %2, %0;" : "+l"(acc) : "l"(a), "l"(b));
}
__device__ __forceinline__ void un2(ull v, float &x, float &y) {
    asm("mov.b64 {%0,%1}, %2;" : "=f"(x), "=f"(y) : "l"(v));
}
__device__ __forceinline__ void cpa16(uint32_t dst, const float* src) {
    asm volatile("cp.async.cg.shared.global [%0], [%1], 16;\n" :: "r"(dst), "l"(src));
}
__device__ __forceinline__ void cpa_commit() {
    asm volatile("cp.async.commit_group;\n" ::: "memory");
}
template<int N> __device__ __forceinline__ void cpa_wait() {
    asm volatile("cp.async.wait_group %0;\n" :: "n"(N) : "memory");
}
__device__ __forceinline__ float vldf(const float* p) { return *(volatile const float*)p; }
__device__ __forceinline__ int   vldi(const int* p)   { return *(volatile const int*)p; }

// grid-wide barrier: all NBLK blocks resident (1 block/SM, 128 <= 148 SMs)
__device__ __forceinline__ void gbar(unsigned &gen) {
    __syncthreads();
    if (threadIdx.x == 0) {
        gen++;
        __threadfence();
        unsigned t = atomicAdd(&g_barcnt, 1);
        if (t == NBLK - 1) {
            g_barcnt = 0;
            __threadfence();
            g_bargen = gen;
        } else {
            while (g_bargen < gen) { __nanosleep(64); }
            __threadfence();
        }
    }
    __syncthreads();
}

// ---------------- tiny reset kernel (per replay) ----------------
__global__ void kI0() {
    int tid = threadIdx.x;
    if (tid < KM) g_counts[tid] = 0;
    if (tid == 0) {
        g_K = 1; g_done = 0; g_prev = 0.0; g_anyfar = 0;
        g_barcnt = 0; g_bargen = 0;
    }
}

// ---------------- persistent mega-kernel ----------------
// P0: x2 (bit-identical to old kI1 order) + column partials, one X pass
// P1: mu[0] = mean, zero rows 1..63, m2
// per iteration (4 grid barriers):
//  A  : fused GEMM (8-wide k-subgroups) + masked min/argmin + anyfar
//  C2 : vectorized scatter-sum partials + counts + non-cf obj partials
//  DF : centroid update + m2; nc rebuild + cf dvals (create iters)
//  G  : obj reduce (double), convergence, commit scalars
#define XPITCH 20
#define STGX (512 * XPITCH * 4)
#define STGB (16 * 16 * 4)
__global__ __launch_bounds__(256) void kMega(const float* __restrict__ X, float* __restrict__ mu) {
    __shared__ __align__(16) float sraw[31616];   // ~123.5 KB, aliased per phase
    const int tid = threadIdx.x, bid = blockIdx.x;
    const int w = tid >> 5, lane = tid & 31;
    unsigned gen = 0;

    // --- phase-A persistent layout ---
    float* sX  = sraw;             // 30720 floats
    float* sB  = sraw + 30720;     // 768
    float* sm2 = sraw + 31488;     // 64
    const int pbase = bid * 512;
    const uint32_t sx0 = (uint32_t)__cvta_generic_to_shared(sX);
    const uint32_t sb0 = (uint32_t)__cvta_generic_to_shared(sB);
    const float* Xr[8]; uint32_t dxo[8];
#pragma unroll
    for (int j = 0; j < 8; j++) {
        int c = tid + 256 * j;
        int row = c >> 2, q = c & 3;
        Xr[j] = X + (size_t)(pbase + row) * DD + 4 * q;
        dxo[j] = sx0 + (uint32_t)(row * (XPITCH * 4) + 16 * q);
    }
    const int bkl = tid >> 2, bq = tid & 3;
    const uint32_t dbb = sb0 + (uint32_t)(bkl * 64 + 16 * bq);
    const int p0 = 64 * w + lane;

    // ===================== P0: x2 + column partials =====================
    {
        float* sacc = sraw;              // [8][1024]
        float racc[32];
#pragma unroll
        for (int j = 0; j < 32; j++) racc[j] = 0.f;
        const float* rowbase = X + (size_t)(pbase + 64 * w) * DD;
        for (int t = 0; t < 64; t++) {
            const float* row = rowbase + (size_t)t * DD;
            float s = 0.f;
#pragma unroll
            for (int j = 0; j < 32; j++) {
                float v = row[lane + 32 * j];
                racc[j] += v;
                s = fmaf(v, v, s);
            }
#pragma unroll
            for (int off = 16; off > 0; off >>= 1) s += __shfl_xor_sync(0xFFFFFFFFu, s, off);
            if (lane == 0) g_x2[pbase + 64 * w + t] = s;
        }
#pragma unroll
        for (int j = 0; j < 32; j++) sacc[w * 1024 + lane + 32 * j] = racc[j];
        __syncthreads();
#pragma unroll
        for (int jj = 0; jj < 4; jj++) {
            int d = tid + 256 * jj;
            float s = 0.f;
#pragma unroll
            for (int ww = 0; ww < 8; ww++) s += sacc[ww * 1024 + d];
            g_colpart2[bid][d] = s;
        }
    }
    gbar(gen);

    // ===================== P1: mu0 / zero rows / m2 =====================
    if (bid == 0) {
        float* smr = sraw;
        float ss = 0.f;
#pragma unroll
        for (int jj = 0; jj < 4; jj++) {
            int d = tid + 256 * jj;
            float s = 0.f;
#pragma unroll 8
            for (int b = 0; b < NBLK; b++) s += vldf(&g_colpart2[b][d]);
            float m = s * (1.0f / 65536.0f);
            mu[d] = m;
            ss = fmaf(m, m, ss);
        }
        smr[tid] = ss;
        __syncthreads();
        for (int off = 128; off > 0; off >>= 1) { if (tid < off) smr[tid] += smr[tid + off]; __syncthreads(); }
        if (tid == 0) g_m2[0] = smr[0];
    } else if (bid < 64) {
#pragma unroll
        for (int jj = 0; jj < 4; jj++) mu[(size_t)bid * DD + tid + 256 * jj] = 0.f;
        if (tid == 0) g_m2[bid] = 0.f;
    }
    gbar(gen);

    const float x2r0 = vldf(g_x2 + pbase + p0);
    const float x2r1 = vldf(g_x2 + pbase + p0 + 32);

    for (int iter = 0; iter < 50; ++iter) {
        if (vldi(&g_done)) break;
        const int K = vldi(&g_K);

        // ===================== Phase A =====================
        if (tid < 64) sm2[tid] = vldf(g_m2 + tid);
        const int kcols = (K + 7) & ~7;         // 8-wide padding
        float best0 = 3.0e38f, best1 = 3.0e38f;
        int bidx0 = 0, bidx1 = 0;

        for (int kbase = 0; kbase < kcols; kbase += 16) {
            const int krem = kcols - kbase;      // multiple of 8
            const bool two = krem > 8;
            const bool bthr = (tid < 64) && (bkl < krem);
            const float* Br = mu + (size_t)(kbase + bkl) * DD + 4 * bq;
            ull a0[4], a1[4], b0[4], b1[4];
#pragma unroll
            for (int m = 0; m < 4; m++) { a0[m] = 0ull; a1[m] = 0ull; b0[m] = 0ull; b1[m] = 0ull; }

            __syncthreads();
#pragma unroll
            for (int s = 0; s < 2; s++) {
                const int db = s * 16;
                const uint32_t ox = (uint32_t)(s * STGX), ob = (uint32_t)(s * STGB);
#pragma unroll
                for (int j = 0; j < 8; j++) cpa16(dxo[j] + ox, Xr[j] + db);
                if (bthr) cpa16(dbb + ob, Br + db);
                cpa_commit();
            }

            for (int s = 0; s < 64; ++s) {
                cpa_wait<1>();
                __syncthreads();
                if (s < 62) {
                    const int sn = s + 2;
                    const int db = sn * 16;
                    const int sl = sn % 3;
                    const uint32_t ox = (uint32_t)(sl * STGX), ob = (uint32_t)(sl * STGB);
#pragma unroll
                    for (int j = 0; j < 8; j++) cpa16(dxo[j] + ox, Xr[j] + db);
                    if (bthr) cpa16(dbb + ob, Br + db);
                }
                cpa_commit();
                {
                    const int sl = s % 3;
                    const float* xb0 = &sX[sl * 512 * XPITCH + p0 * XPITCH];
                    const float* xb1 = xb0 + 32 * XPITCH;
                    const float* bb = &sB[sl * 256];
#pragma unroll
                    for (int q = 0; q < 4; q++) {
                        float4 x0 = *reinterpret_cast<const float4*>(xb0 + 4 * q);
                        float4 x1 = *reinterpret_cast<const float4*>(xb1 + 4 * q);
                        ull xp0[4], xp1[4];
                        xp0[0] = pk2(x0.x, x0.x); xp0[1] = pk2(x0.y, x0.y);
                        xp0[2] = pk2(x0.z, x0.z); xp0[3] = pk2(x0.w, x0.w);
                        xp1[0] = pk2(x1.x, x1.x); xp1[1] = pk2(x1.y, x1.y);
                        xp1[2] = pk2(x1.z, x1.z); xp1[3] = pk2(x1.w, x1.w);
#pragma unroll
                        for (int m = 0; m < 4; m++) {
                            float4 bA  = *reinterpret_cast<const float4*>(bb + (2 * m) * 16 + 4 * q);
                            float4 bBv = *reinterpret_cast<const float4*>(bb + (2 * m + 1) * 16 + 4 * q);
                            ull bp0 = pk2(bA.x, bBv.x), bp1 = pk2(bA.y, bBv.y);
                            ull bp2 = pk2(bA.z, bBv.z), bp3 = pk2(bA.w, bBv.w);
                            fma2(a0[m], xp0[0], bp0); fma2(a0[m], xp0[1], bp1);
                            fma2(a0[m], xp0[2], bp2); fma2(a0[m], xp0[3], bp3);
                            fma2(a1[m], xp1[0], bp0); fma2(a1[m], xp1[1], bp1);
                            fma2(a1[m], xp1[2], bp2); fma2(a1[m], xp1[3], bp3);
                        }
                        if (two) {
#pragma unroll
                            for (int m = 0; m < 4; m++) {
                                float4 bA  = *reinterpret_cast<const float4*>(bb + (8 + 2 * m) * 16 + 4 * q);
                                float4 bBv = *reinterpret_cast<const float4*>(bb + (9 + 2 * m) * 16 + 4 * q);
                                ull bp0 = pk2(bA.x, bBv.x), bp1 = pk2(bA.y, bBv.y);
                                ull bp2 = pk2(bA.z, bBv.z), bp3 = pk2(bA.w, bBv.w);
                                fma2(b0[m], xp0[0], bp0); fma2(b0[m], xp0[1], bp1);
                                fma2(b0[m], xp0[2], bp2); fma2(b0[m], xp0[3], bp3);
                                fma2(b1[m], xp1[0], bp0); fma2(b1[m], xp1[1], bp1);
                                fma2(b1[m], xp1[2], bp2); fma2(b1[m], xp1[3], bp3);
                            }
                        }
                    }
                }
            }

            // epilogue: subgroup 0 then subgroup 1 (ascending k => first-index ties)
#pragma unroll
            for (int m = 0; m < 4; m++) {
                int k0 = kbase + 2 * m;
                float s0, s1; un2(a0[m], s0, s1);
                float d0 = fmaf(-2.f, s0, x2r0) + sm2[k0];
                float d1 = fmaf(-2.f, s1, x2r0) + sm2[k0 + 1];
                if (k0 < K && d0 < best0) { best0 = d0; bidx0 = k0; }
                if (k0 + 1 < K && d1 < best0) { best0 = d1; bidx0 = k0 + 1; }
                un2(a1[m], s0, s1);
                float e0 = fmaf(-2.f, s0, x2r1) + sm2[k0];
                float e1 = fmaf(-2.f, s1, x2r1) + sm2[k0 + 1];
                if (k0 < K && e0 < best1) { best1 = e0; bidx1 = k0; }
                if (k0 + 1 < K && e1 < best1) { best1 = e1; bidx1 = k0 + 1; }
            }
            if (two) {
#pragma unroll
                for (int m = 0; m < 4; m++) {
                    int k0 = kbase + 8 + 2 * m;
                    float s0, s1; un2(b0[m], s0, s1);
                    float d0 = fmaf(-2.f, s0, x2r0) + sm2[k0];
                    float d1 = fmaf(-2.f, s1, x2r0) + sm2[k0 + 1];
                    if (k0 < K && d0 < best0) { best0 = d0; bidx0 = k0; }
                    if (k0 + 1 < K && d1 < best0) { best0 = d1; bidx0 = k0 + 1; }
                    un2(b1[m], s0, s1);
                    float e0 = fmaf(-2.f, s0, x2r1) + sm2[k0];
                    float e1 = fmaf(-2.f, s1, x2r1) + sm2[k0 + 1];
                    if (k0 < K && e0 < best1) { best1 = e0; bidx1 = k0; }
                    if (k0 + 1 < K && e1 < best1) { best1 = e1; bidx1 = k0 + 1; }
                }
            }
        }

        g_dmin[pbase + p0] = best0;       g_ztmp[pbase + p0] = bidx0;
        g_dmin[pbase + p0 + 32] = best1;  g_ztmp[pbase + p0 + 32] = bidx1;
        {
            bool farflag = (best0 > 1000.f) || (best1 > 1000.f);
            unsigned b = __ballot_sync(0xFFFFFFFFu, farflag);
            if (b && lane == 0) atomicOr(&g_anyfar, 1);
        }
        gbar(gen);

        // ------- iteration bookkeeping (uniform across blocks) -------
        const int create = (vldi(&g_anyfar) != 0) && (K < KM);
        const int Kc = K;
        const int Knew = K + create;
        const int kmax = min(KM, (Knew + 15) & ~15);
        const int nk2 = kmax >> 4;

        // ===================== Phase C2 =====================
        {
            const int h = tid >> 7, t128 = tid & 127;
            float4* acc4 = reinterpret_cast<float4*>(sraw) + h * 2048;
            int* zsh  = reinterpret_cast<int*>(sraw + 16384) + h * 1024;
            int* scnt = reinterpret_cast<int*>(sraw + 18432);
            float* ored = sraw + 18496;
            if (bid < 64 && tid < 64) scnt[tid] = 0;
            float objs = 0.f;
            const int c = t128 & 31, pg = t128 >> 5;

            for (int jo = 0; jo < 2; jo++) {
                const int unit = (jo * 2 + h) * 128 + bid;
                const int dchunk = unit >> 6, pblk = unit & 63;
                const int dbase = dchunk * 128, pb = pblk * 1024;
                const bool docount = (jo == 0) && (h == 0) && (bid < 64);
                __syncthreads();
#pragma unroll
                for (int q = 0; q < 8; q++) {
                    int ip = pb + q * 128 + t128;
                    float dmv = vldf(g_dmin + ip);
                    int ztv = vldi(g_ztmp + ip);
                    bool cf = create && (dmv > 1000.f);
                    int z = cf ? Kc : ztv;
                    zsh[q * 128 + t128] = z;
                    if (docount) { atomicAdd(&scnt[z], 1); if (!cf) objs += dmv; }
                }
                const float* xp = X + (size_t)(pb + pg * 256) * DD + dbase + 4 * c;
                for (int kg2 = 0; kg2 < nk2; kg2++) {
                    __syncthreads();
#pragma unroll
                    for (int kk = 0; kk < 16; kk++)
                        acc4[(pg * 16 + kk) * 32 + c] = make_float4(0.f, 0.f, 0.f, 0.f);
                    __syncthreads();
#pragma unroll 4
                    for (int t = 0; t < 256; t++) {
                        float4 v = *reinterpret_cast<const float4*>(xp + (size_t)t * DD);
                        int zr = zsh[pg * 256 + t] - (kg2 << 4);
                        if ((unsigned)zr < 16u) {
                            float4 a = acc4[(pg * 16 + zr) * 32 + c];
                            a.x += v.x; a.y += v.y; a.z += v.z; a.w += v.w;
                            acc4[(pg * 16 + zr) * 32 + c] = a;
                        }
                    }
                    __syncthreads();
#pragma unroll
                    for (int kb = 0; kb < 16; kb += 4) {
                        int kloc = kb + (t128 >> 5);
                        float4 s0 = acc4[(0 * 16 + kloc) * 32 + c];
                        float4 s1 = acc4[(1 * 16 + kloc) * 32 + c];
                        float4 s2 = acc4[(2 * 16 + kloc) * 32 + c];
                        float4 s3 = acc4[(3 * 16 + kloc) * 32 + c];
                        float4 o;
                        o.x = ((s0.x + s1.x) + s2.x) + s3.x;
                        o.y = ((s0.y + s1.y) + s2.y) + s3.y;
                        o.z = ((s0.z + s1.z) + s2.z) + s3.z;
                        o.w = ((s0.w + s1.w) + s2.w) + s3.w;
                        *reinterpret_cast<float4*>(&g_sumpart[dchunk][pblk][kg2 * 16 + kloc][4 * c]) = o;
                    }
                }
            }
            __syncthreads();
            if (bid < 64) {
                ored[tid] = (h == 0) ? objs : 0.f;
                __syncthreads();
                for (int off = 128; off > 0; off >>= 1) { if (tid < off) ored[tid] += ored[tid + off]; __syncthreads(); }
                if (tid == 0) g_objA[bid] = ored[0];
                if (tid < 64 && scnt[tid]) atomicAdd(&g_counts[tid], scnt[tid]);
            }
        }
        gbar(gen);

        // ===================== Phase D+F =====================
        if (bid < Knew) {
            float* smr = sraw + 2048;
            const int k = bid;
            const int cnt = vldi(g_counts + k);
            float ss = 0.f;
#pragma unroll
            for (int jo2 = 0; jo2 < 4; jo2++) {
                int d = tid + 256 * jo2;
                float s = 0.f;
#pragma unroll 8
                for (int pb2 = 0; pb2 < 64; pb2++)
                    s += vldf(&g_sumpart[d >> 7][pb2][k][d & 127]);
                float mv;
                if (cnt > 0) { mv = s / (float)cnt; mu[(size_t)k * DD + d] = mv; }
                else mv = vldf(&mu[(size_t)k * DD + d]);
                ss = fmaf(mv, mv, ss);
            }
            smr[tid] = ss;
            __syncthreads();
            for (int off = 128; off > 0; off >>= 1) { if (tid < off) smr[tid] += smr[tid + off]; __syncthreads(); }
            if (tid == 0) g_m2[k] = smr[0];
        }
        if (create) {
            float* snc = sraw;           // 1024
            float* wred = sraw + 1088;   // 8
            const int cntc = vldi(g_counts + Kc);
#pragma unroll
            for (int jo2 = 0; jo2 < 4; jo2++) {
                int d = tid + 256 * jo2;
                float s = 0.f;
#pragma unroll 8
                for (int pb2 = 0; pb2 < 64; pb2++)
                    s += vldf(&g_sumpart[d >> 7][pb2][Kc][d & 127]);
                snc[d] = s / (float)cntc;      // == mu[Kc][d] bit-identical
            }
            __syncthreads();
            float objw = 0.f;
            for (int t = 0; t < 64; t++) {
                int i = pbase + w * 64 + t;
                float dmv = vldf(g_dmin + i);
                if (dmv > 1000.f) {
                    const float* row = X + (size_t)i * DD;
                    float s = 0.f;
#pragma unroll
                    for (int j = 0; j < 32; j++) {
                        int d = lane + 32 * j;
                        float dv = row[d] - snc[d];
                        s = fmaf(dv, dv, s);
                    }
#pragma unroll
                    for (int off = 16; off > 0; off >>= 1) s += __shfl_xor_sync(0xFFFFFFFFu, s, off);
                    objw += s;
                }
            }
            if (lane == 0) wred[w] = objw;
            __syncthreads();
            if (tid == 0) {
                float s = 0.f;
                for (int q = 0; q < 8; q++) s += wred[q];
                g_objF[bid] = s;
            }
        } else if (tid == 0) g_objF[bid] = 0.f;
        gbar(gen);

        // ===================== Phase G =====================
        if (bid == 0) {
            double* sd = reinterpret_cast<double*>(sraw);
            double v = 0.0;
            if (tid < 64) v += (double)vldf(g_objA + tid);
            if (tid >= 64 && tid < 64 + NBLK) v += (double)vldf(g_objF + (tid - 64));
            sd[tid] = v;
            __syncthreads();
            for (int off = 128; off > 0; off >>= 1) { if (tid < off) sd[tid] += sd[tid + off]; __syncthreads(); }
            if (tid == 0) {
                double obj = sd[0] + 1000.0 * (double)Knew;
                bool conv = (iter > 0) && (fabs(obj - g_prev) < 1e-3 * obj);
                g_prev = obj;
                *(volatile int*)&g_K = Knew;
                *(volatile int*)&g_anyfar = 0;
                if (conv) *(volatile int*)&g_done = 1;
            }
            if (tid < 64) *(volatile int*)(g_counts + tid) = 0;
        }
        gbar(gen);
    }
}

// ---------------- launch ----------------
extern "C" void kernel_launch(void* const* d_in, const int* in_sizes, int n_in,
                              void* d_out, int out_size) {
    const float* X = (const float*)d_in[0];
    float* mu = (float*)d_out;   // d_out (1,64,1024) doubles as the live centroid buffer

    kI0<<<1, 256>>>();
    kMega<<<NBLK, 256>>>(X, mu);
}